// round 1
// baseline (speedup 1.0000x reference)
#include <cuda_runtime.h>
#include <cuda_bf16.h>

// ---------------------------------------------------------------------------
// TR_Linear: y = x @ W.T + bias with W built from a tensor ring.
// Factored through the ring into two fp32 GEMMs (34.4 GFLOP total instead of
// 68.7 dense):
//   Pp[i', n]  (1024x1024), n = (r2*16+r4)*4 + h
//   C1 = x @ Pp                    (8192x1024, K=1024)
//   Q2[k, n2]  (256x1024), k = r2*16+r4, n2 = i0*32+i1
//   y[b, n2*4+h] = sum_k C1[b, k*4+h] * Q2[k, n2] + bias[n2*4+h]
// Index mapping derived from w.reshape(4096, 1024) of the (i0,i1,o0,o1) tensor:
//   o' = i0*128 + i1*4 + h ;  i' = (o0_lo4 << 6) | o1 ; o0 = h*16 + o0_lo4
// ---------------------------------------------------------------------------

#define M_ROWS 8192
#define K1 1024
#define N1 1024
#define K2 256
#define N2 1024
#define NOUT 4096

__device__ float g_Pp[K1 * N1];        // 4 MB
__device__ float g_Q2[K2 * N2];        // 1 MB
__device__ float g_C1[M_ROWS * N1];    // 32 MB

// --- Pp[i'*1024 + n] = sum_r3 core2[r2, h*16+(i'>>6), r3] * core3[r3, i'&63, r4]
__global__ void build_Pp_kernel(const float* __restrict__ c2,
                                const float* __restrict__ c3) {
    int idx = blockIdx.x * blockDim.x + threadIdx.x;
    if (idx >= K1 * N1) return;
    int n  = idx & 1023;
    int ip = idx >> 10;
    int r2 = n >> 6;
    int r4 = (n >> 2) & 15;
    int h  = n & 3;
    int o0 = h * 16 + (ip >> 6);
    int o1 = ip & 63;
    const float* a = c2 + (r2 * 64 + o0) * 16;   // over r3
    float s = 0.f;
#pragma unroll
    for (int r3 = 0; r3 < 16; r3++)
        s += a[r3] * c3[(r3 * 64 + o1) * 16 + r4];
    g_Pp[idx] = s;
}

// --- Q2[k*1024 + n2] = sum_r1 core0[r4, i0, r1] * core1[r1, i1, r2]
__global__ void build_Q2_kernel(const float* __restrict__ c0,
                                const float* __restrict__ c1) {
    int idx = blockIdx.x * blockDim.x + threadIdx.x;
    if (idx >= K2 * N2) return;
    int n2 = idx & 1023;
    int k  = idx >> 10;
    int r2 = k >> 4;
    int r4 = k & 15;
    int i0 = n2 >> 5;
    int i1 = n2 & 31;
    const float* a = c0 + (r4 * 32 + i0) * 16;   // over r1
    float s = 0.f;
#pragma unroll
    for (int r1 = 0; r1 < 16; r1++)
        s += a[r1] * c1[(r1 * 32 + i1) * 16 + r2];
    g_Q2[idx] = s;
}

// --- GEMM1: C1[M,1024] = x[M,1024] @ Pp[1024,1024]   (row-major everywhere)
// Tiles: 64x64x16, 256 threads, 4x4 per thread.
__global__ __launch_bounds__(256) void gemm1_kernel(const float* __restrict__ A) {
    __shared__ float Ast[16][64];   // transposed: [k][m]
    __shared__ float Bs[16][64];    // [k][n]

    const float* B = g_Pp;
    int t  = threadIdx.x;
    int bm = blockIdx.y * 64;
    int bn = blockIdx.x * 64;
    int tx = t & 15;
    int ty = t >> 4;

    float acc[4][4];
#pragma unroll
    for (int i = 0; i < 4; i++)
#pragma unroll
        for (int j = 0; j < 4; j++) acc[i][j] = 0.f;

    int arow = t >> 2;            // 0..63
    int acg  = (t & 3) * 4;       // k offset within tile, float4
    int brow = t >> 4;            // 0..15
    int bcg  = (t & 15) * 4;      // n offset, float4

    const float* Ag = A + (bm + arow) * K1;

    for (int k0 = 0; k0 < K1; k0 += 16) {
        float4 av = *(const float4*)(Ag + k0 + acg);
        float4 bv = *(const float4*)(B + (k0 + brow) * N1 + bn + bcg);
        __syncthreads();
        Ast[acg + 0][arow] = av.x;
        Ast[acg + 1][arow] = av.y;
        Ast[acg + 2][arow] = av.z;
        Ast[acg + 3][arow] = av.w;
        *(float4*)&Bs[brow][bcg] = bv;
        __syncthreads();
#pragma unroll
        for (int kk = 0; kk < 16; kk++) {
            float4 a = *(const float4*)&Ast[kk][ty * 4];
            float4 b = *(const float4*)&Bs[kk][tx * 4];
            acc[0][0] += a.x * b.x; acc[0][1] += a.x * b.y; acc[0][2] += a.x * b.z; acc[0][3] += a.x * b.w;
            acc[1][0] += a.y * b.x; acc[1][1] += a.y * b.y; acc[1][2] += a.y * b.z; acc[1][3] += a.y * b.w;
            acc[2][0] += a.z * b.x; acc[2][1] += a.z * b.y; acc[2][2] += a.z * b.z; acc[2][3] += a.z * b.w;
            acc[3][0] += a.w * b.x; acc[3][1] += a.w * b.y; acc[3][2] += a.w * b.z; acc[3][3] += a.w * b.w;
        }
    }

#pragma unroll
    for (int i = 0; i < 4; i++) {
        float4 v = make_float4(acc[i][0], acc[i][1], acc[i][2], acc[i][3]);
        *(float4*)(g_C1 + (bm + ty * 4 + i) * (long)N1 + bn + tx * 4) = v;
    }
}

// --- GEMM2 (grouped over h): y[b, n2*4+h] = sum_k C1[b, k*4+h]*Q2[k,n2] + bias
// Block: 64 rows x 32 n2-cols x all 4 h. 256 threads, each 4m x 2n2 x 4h.
__global__ __launch_bounds__(256) void gemm2_kernel(const float* __restrict__ bias,
                                                    float* __restrict__ Y) {
    __shared__ float As[64][68];    // [m][kk*4+h], padded (68 floats, 16B-mult)
    __shared__ float Bs[16][32];    // [kk][n2]

    const float* A = g_C1;
    const float* B = g_Q2;
    int t   = threadIdx.x;
    int bm  = blockIdx.y * 64;
    int bn2 = blockIdx.x * 32;
    int tm  = t >> 4;     // 0..15
    int tn  = t & 15;     // 0..15

    float acc[4][4][2];   // [mi][h][nj]
#pragma unroll
    for (int a = 0; a < 4; a++)
#pragma unroll
        for (int b = 0; b < 4; b++) { acc[a][b][0] = 0.f; acc[a][b][1] = 0.f; }

    int arow = t >> 2;           // 0..63
    int acg  = (t & 3) * 16;     // 16 floats per thread: 4 x float4

    for (int k0 = 0; k0 < K2; k0 += 16) {
        float4 av[4];
#pragma unroll
        for (int j = 0; j < 4; j++)
            av[j] = *(const float4*)(A + (bm + arow) * (long)N1 + k0 * 4 + acg + j * 4);
        float2 bv = *(const float2*)(B + (k0 + (t >> 4)) * N2 + bn2 + (t & 15) * 2);
        __syncthreads();
#pragma unroll
        for (int j = 0; j < 4; j++)
            *(float4*)&As[arow][acg + j * 4] = av[j];
        *(float2*)&Bs[t >> 4][(t & 15) * 2] = bv;
        __syncthreads();
#pragma unroll
        for (int kk = 0; kk < 16; kk++) {
            float b0 = Bs[kk][tn * 2 + 0];
            float b1 = Bs[kk][tn * 2 + 1];
#pragma unroll
            for (int mi = 0; mi < 4; mi++) {
                float4 a = *(const float4*)&As[tm * 4 + mi][kk * 4];
                acc[mi][0][0] += a.x * b0; acc[mi][0][1] += a.x * b1;
                acc[mi][1][0] += a.y * b0; acc[mi][1][1] += a.y * b1;
                acc[mi][2][0] += a.z * b0; acc[mi][2][1] += a.z * b1;
                acc[mi][3][0] += a.w * b0; acc[mi][3][1] += a.w * b1;
            }
        }
    }

    // Epilogue: for each n2, the 4 h-values are 4 consecutive output floats.
#pragma unroll
    for (int nj = 0; nj < 2; nj++) {
        int n2 = bn2 + tn * 2 + nj;
        float4 bz = *(const float4*)(bias + n2 * 4);
#pragma unroll
        for (int mi = 0; mi < 4; mi++) {
            float4 v = make_float4(acc[mi][0][nj] + bz.x,
                                   acc[mi][1][nj] + bz.y,
                                   acc[mi][2][nj] + bz.z,
                                   acc[mi][3][nj] + bz.w);
            *(float4*)(Y + (bm + tm * 4 + mi) * (long)NOUT + n2 * 4) = v;
        }
    }
}

extern "C" void kernel_launch(void* const* d_in, const int* in_sizes, int n_in,
                              void* d_out, int out_size) {
    const float* x     = (const float*)d_in[0];
    const float* core0 = (const float*)d_in[1];
    const float* core1 = (const float*)d_in[2];
    const float* core2 = (const float*)d_in[3];
    const float* core3 = (const float*)d_in[4];
    const float* bias  = (const float*)d_in[5];
    float* y = (float*)d_out;

    build_Pp_kernel<<<(K1 * N1) / 256, 256>>>(core2, core3);
    build_Q2_kernel<<<(K2 * N2) / 256, 256>>>(core0, core1);

    {
        dim3 grid(N1 / 64, M_ROWS / 64);
        gemm1_kernel<<<grid, 256>>>(x);
    }
    {
        dim3 grid(N2 / 32, M_ROWS / 64);
        gemm2_kernel<<<grid, 256>>>(bias, y);
    }
}

// round 3
// speedup vs baseline: 1.4678x; 1.4678x over previous
#include <cuda_runtime.h>
#include <cuda_bf16.h>
#include <cstdint>

// ---------------------------------------------------------------------------
// TR_Linear via two bf16-split GEMMs on the tensor pipe through PORTABLE PTX
// (mma.sync.m16n8k16.bf16 / ldmatrix / cp.async) -- tcgen05 is unavailable in
// this harness build (PTX target compute_103 without 'a').
//   Pp^T[n][i'] (1024x1024), n=(r2*16+r4)*4+h ;  C1 = x @ Pp  (K=1024)
//   Q2^T[n2][k] (1024x256),  k=r2*16+r4, n2=i0*32+i1
//   y[b, n2*4+h] = sum_k C1[b,k*4+h]*Q2[k,n2] + bias
// Precision: v = hi + lo (bf16); D += Ahi*Bhi + Ahi*Blo + Alo*Bhi (fp32 acc)
// ---------------------------------------------------------------------------

#define MTOT 8192
#define PAD 40   // bf16 elems per 32-elem k-row (80B stride -> conflict-free ldmatrix)

typedef __nv_bfloat16 bf16;

__device__ bf16 g_xh[MTOT * 1024];
__device__ bf16 g_xl[MTOT * 1024];
__device__ bf16 g_pph[1024 * 1024];
__device__ bf16 g_ppl[1024 * 1024];
__device__ bf16 g_q2h[1024 * 256];
__device__ bf16 g_q2l[1024 * 256];
__device__ bf16 g_c1h[4 * MTOT * 256];   // [h][b][k2]
__device__ bf16 g_c1l[4 * MTOT * 256];

// ========================= PTX helpers (portable) ==========================
__device__ __forceinline__ void cp16(uint32_t dst, const void* src) {
    asm volatile("cp.async.cg.shared.global [%0], [%1], 16;" :: "r"(dst), "l"(src));
}
#define CP_COMMIT() asm volatile("cp.async.commit_group;" ::: "memory")
#define CP_WAIT(N)  asm volatile("cp.async.wait_group %0;" :: "n"(N) : "memory")

__device__ __forceinline__ void ldm4(uint32_t& r0, uint32_t& r1, uint32_t& r2, uint32_t& r3,
                                     uint32_t addr) {
    asm volatile("ldmatrix.sync.aligned.m8n8.x4.shared.b16 {%0,%1,%2,%3}, [%4];"
                 : "=r"(r0), "=r"(r1), "=r"(r2), "=r"(r3) : "r"(addr));
}
__device__ __forceinline__ void mma_bf16(float* d, const uint32_t* a, const uint32_t* b) {
    asm volatile("mma.sync.aligned.m16n8k16.row.col.f32.bf16.bf16.f32 "
                 "{%0,%1,%2,%3}, {%4,%5,%6,%7}, {%8,%9}, {%0,%1,%2,%3};"
                 : "+f"(d[0]), "+f"(d[1]), "+f"(d[2]), "+f"(d[3])
                 : "r"(a[0]), "r"(a[1]), "r"(a[2]), "r"(a[3]), "r"(b[0]), "r"(b[1]));
}
__device__ __forceinline__ uint32_t cvta_s(const void* p) {
    return (uint32_t)__cvta_generic_to_shared(p);
}
__device__ __forceinline__ void split2(float v, bf16& h, bf16& l) {
    h = __float2bfloat16_rn(v);
    l = __float2bfloat16_rn(v - __bfloat162float(h));
}

// ========================= prepass kernels =================================
__global__ void conv_x_kernel(const float* __restrict__ x) {
    int i = blockIdx.x * blockDim.x + threadIdx.x;
    bf16 h, l;
    split2(x[i], h, l);
    g_xh[i] = h;
    g_xl[i] = l;
}

__global__ void build_pp_kernel(const float* __restrict__ c2, const float* __restrict__ c3) {
    int idx = blockIdx.x * blockDim.x + threadIdx.x;   // n*1024 + i'
    int n = idx >> 10, ip = idx & 1023;
    int r2 = n >> 6, r4 = (n >> 2) & 15, h = n & 3;
    int o0 = h * 16 + (ip >> 6), o1 = ip & 63;
    const float* a = c2 + (r2 * 64 + o0) * 16;
    float s = 0.f;
#pragma unroll
    for (int r3 = 0; r3 < 16; r3++) s += a[r3] * c3[(r3 * 64 + o1) * 16 + r4];
    bf16 hh, ll;
    split2(s, hh, ll);
    g_pph[idx] = hh;
    g_ppl[idx] = ll;
}

__global__ void build_q2_kernel(const float* __restrict__ c0, const float* __restrict__ c1) {
    int idx = blockIdx.x * blockDim.x + threadIdx.x;   // n2*256 + k
    int n2 = idx >> 8, k = idx & 255;
    int r2 = k >> 4, r4 = k & 15;
    int i0 = n2 >> 5, i1 = n2 & 31;
    const float* a = c0 + (r4 * 32 + i0) * 16;
    float s = 0.f;
#pragma unroll
    for (int r1 = 0; r1 < 16; r1++) s += a[r1] * c1[(r1 * 32 + i1) * 16 + r2];
    bf16 hh, ll;
    split2(s, hh, ll);
    g_q2h[idx] = hh;
    g_q2l[idx] = ll;
}

// ========================= GEMM1: C1 = x @ Pp ==============================
// 128x128 block, K=1024 in 32 chunks of 32. smem arrays per stage:
// [Ah, Al, Bh, Bl] each 128 rows x PAD bf16. SLOT = 4*128*PAD bf16 = 40960B.
#define G1_SLOT (4 * 128 * PAD)
#define G1_SMEM (2 * G1_SLOT * 2)

__global__ __launch_bounds__(256, 2) void gemm1_mma() {
    extern __shared__ char dsm[];
    bf16* sm = (bf16*)dsm;
    const int t = threadIdx.x, wid = t >> 5, lane = t & 31;
    const int bm = blockIdx.y * 128, bn = blockIdx.x * 128;
    const int wm = wid & 1, wn = wid >> 1;     // warp tile 64m x 32n

    float acc[4][4][4];
#pragma unroll
    for (int a = 0; a < 4; a++)
#pragma unroll
        for (int b = 0; b < 4; b++)
#pragma unroll
            for (int c = 0; c < 4; c++) acc[a][b][c] = 0.f;

    auto load_stage = [&](int s, int k0) {
#pragma unroll
        for (int i = 0; i < 8; i++) {
            int gi = i * 256 + t;
            int arr = gi >> 9, rem = gi & 511, row = rem >> 2, c = rem & 3;
            const bf16* src;
            if (arr == 0)      src = g_xh  + (size_t)(bm + row) * 1024 + k0 + c * 8;
            else if (arr == 1) src = g_xl  + (size_t)(bm + row) * 1024 + k0 + c * 8;
            else if (arr == 2) src = g_pph + (size_t)(bn + row) * 1024 + k0 + c * 8;
            else               src = g_ppl + (size_t)(bn + row) * 1024 + k0 + c * 8;
            cp16(cvta_s(sm + s * G1_SLOT + arr * 128 * PAD + row * PAD + c * 8), src);
        }
    };

    const int lr = lane & 15, lc = lane >> 4;

    auto compute = [&](int s) {
        uint32_t abase = cvta_s(sm) + (uint32_t)(s * G1_SLOT) * 2;
#pragma unroll
        for (int kk = 0; kk < 2; kk++) {
            uint32_t ah[4][4], al[4][4], bb[4][2];
            uint32_t koff = (uint32_t)((kk * 2 + lc) * 8) * 2;
#pragma unroll
            for (int mi = 0; mi < 4; mi++) {
                uint32_t off = (uint32_t)((wm * 64 + mi * 16 + lr) * PAD) * 2 + koff;
                ldm4(ah[mi][0], ah[mi][1], ah[mi][2], ah[mi][3], abase + off);
                ldm4(al[mi][0], al[mi][1], al[mi][2], al[mi][3],
                     abase + 128 * PAD * 2 + off);
            }
#pragma unroll
            for (int p = 0; p < 2; p++) {
                uint32_t off = (uint32_t)((wn * 32 + p * 16 + lr) * PAD) * 2 + koff;
                uint32_t r0, r1, r2, r3;
                ldm4(r0, r1, r2, r3, abase + 2 * 128 * PAD * 2 + off);
                bb[2 * p][0] = r0; bb[2 * p][1] = r2;
                bb[2 * p + 1][0] = r1; bb[2 * p + 1][1] = r3;
            }
#pragma unroll
            for (int mi = 0; mi < 4; mi++)
#pragma unroll
                for (int ni = 0; ni < 4; ni++) {
                    mma_bf16(acc[mi][ni], ah[mi], bb[ni]);   // Ahi*Bhi
                }
#pragma unroll
            for (int mi = 0; mi < 4; mi++)
#pragma unroll
                for (int ni = 0; ni < 4; ni++) {
                    mma_bf16(acc[mi][ni], al[mi], bb[ni]);   // Alo*Bhi
                }
#pragma unroll
            for (int p = 0; p < 2; p++) {
                uint32_t off = (uint32_t)((wn * 32 + p * 16 + lr) * PAD) * 2 + koff;
                uint32_t r0, r1, r2, r3;
                ldm4(r0, r1, r2, r3, abase + 3 * 128 * PAD * 2 + off);
                bb[2 * p][0] = r0; bb[2 * p][1] = r2;
                bb[2 * p + 1][0] = r1; bb[2 * p + 1][1] = r3;
            }
#pragma unroll
            for (int mi = 0; mi < 4; mi++)
#pragma unroll
                for (int ni = 0; ni < 4; ni++) {
                    mma_bf16(acc[mi][ni], ah[mi], bb[ni]);   // Ahi*Blo
                }
        }
    };

    load_stage(0, 0);
    CP_COMMIT();
    for (int kc = 0; kc < 32; kc++) {
        if (kc + 1 < 32) {
            load_stage((kc + 1) & 1, (kc + 1) * 32);
            CP_COMMIT();
            CP_WAIT(1);
        } else {
            CP_WAIT(0);
        }
        __syncthreads();
        compute(kc & 1);
        __syncthreads();
    }

    // ---- epilogue: stage fp32 tile, then bf16-split into C1[h][b][k2] ----
    float* stg = (float*)dsm;     // [128][132]
#pragma unroll
    for (int mi = 0; mi < 4; mi++)
#pragma unroll
        for (int ni = 0; ni < 4; ni++) {
            int r = wm * 64 + mi * 16 + (lane >> 2);
            int c = wn * 32 + ni * 8 + (lane & 3) * 2;
            stg[r * 132 + c]           = acc[mi][ni][0];
            stg[r * 132 + c + 1]       = acc[mi][ni][1];
            stg[(r + 8) * 132 + c]     = acc[mi][ni][2];
            stg[(r + 8) * 132 + c + 1] = acc[mi][ni][3];
        }
    __syncthreads();

    const int kb = bn >> 2;
#pragma unroll
    for (int i = 0; i < 16; i++) {
        int g = i * 256 + t;                   // 4096 groups of 4 k2
        int row = g >> 5, rem = g & 31, h = rem >> 3, kg = rem & 7;
        ushort4 vh, vl;
        bf16 hh, ll;
        split2(stg[row * 132 + (kg * 4 + 0) * 4 + h], hh, ll);
        vh.x = __bfloat16_as_ushort(hh); vl.x = __bfloat16_as_ushort(ll);
        split2(stg[row * 132 + (kg * 4 + 1) * 4 + h], hh, ll);
        vh.y = __bfloat16_as_ushort(hh); vl.y = __bfloat16_as_ushort(ll);
        split2(stg[row * 132 + (kg * 4 + 2) * 4 + h], hh, ll);
        vh.z = __bfloat16_as_ushort(hh); vl.z = __bfloat16_as_ushort(ll);
        split2(stg[row * 132 + (kg * 4 + 3) * 4 + h], hh, ll);
        vh.w = __bfloat16_as_ushort(hh); vl.w = __bfloat16_as_ushort(ll);
        size_t o = ((size_t)h * MTOT + bm + row) * 256 + kb + kg * 4;
        *(ushort4*)(g_c1h + o) = vh;
        *(ushort4*)(g_c1l + o) = vl;
    }
}

// ========================= GEMM2: y = C1_h @ Q2^T + bias ===================
// Block: 64b x 64n2 x 4h. K=256 in 8 chunks of 32.
// smem per stage (bf16): Ah[4*64][PAD] @0, Al @10240, Bh[64][PAD] @20480, Bl @23040
#define G2_SLOT 25600
#define G2_SMEM (2 * G2_SLOT * 2)

__global__ __launch_bounds__(256, 2) void gemm2_mma(const float* __restrict__ bias,
                                                    float* __restrict__ Y) {
    extern __shared__ char dsm[];
    bf16* sm = (bf16*)dsm;
    const int t = threadIdx.x, wid = t >> 5, lane = t & 31;
    const int bm = blockIdx.y * 64, bn2 = blockIdx.x * 64;
    const int wh = wid >> 1, mh = wid & 1;     // warp: h = wh, rows mh*32..+31

    float acc[2][8][4];
#pragma unroll
    for (int a = 0; a < 2; a++)
#pragma unroll
        for (int b = 0; b < 8; b++)
#pragma unroll
            for (int c = 0; c < 4; c++) acc[a][b][c] = 0.f;

    auto load_stage = [&](int s, int k0) {
#pragma unroll
        for (int i = 0; i < 10; i++) {
            int gi = i * 256 + t;
            if (gi < 2048) {               // A: 2 planes x 4h x 64 rows x 4 chunks
                int plane = gi >> 10, rem = gi & 1023;
                int h = rem >> 8, rem2 = rem & 255, row = rem2 >> 2, c = rem2 & 3;
                const bf16* src = (plane ? g_c1l : g_c1h) +
                    ((size_t)h * MTOT + bm + row) * 256 + k0 + c * 8;
                cp16(cvta_s(sm + s * G2_SLOT + plane * 10240 + (h * 64 + row) * PAD + c * 8), src);
            } else {                       // B: 2 planes x 64 rows x 4 chunks
                int b = gi - 2048;
                int plane = b >> 8, rem = b & 255, row = rem >> 2, c = rem & 3;
                const bf16* src = (plane ? g_q2l : g_q2h) +
                    (size_t)(bn2 + row) * 256 + k0 + c * 8;
                cp16(cvta_s(sm + s * G2_SLOT + 20480 + plane * 2560 + row * PAD + c * 8), src);
            }
        }
    };

    const int lr = lane & 15, lc = lane >> 4;

    auto compute = [&](int s) {
        uint32_t abase = cvta_s(sm) + (uint32_t)(s * G2_SLOT) * 2;
#pragma unroll
        for (int kk = 0; kk < 2; kk++) {
            uint32_t ah[2][4], al[2][4], bb[8][2];
            uint32_t koff = (uint32_t)((kk * 2 + lc) * 8) * 2;
#pragma unroll
            for (int mi = 0; mi < 2; mi++) {
                uint32_t off = (uint32_t)((wh * 64 + mh * 32 + mi * 16 + lr) * PAD) * 2 + koff;
                ldm4(ah[mi][0], ah[mi][1], ah[mi][2], ah[mi][3], abase + off);
                ldm4(al[mi][0], al[mi][1], al[mi][2], al[mi][3],
                     abase + 10240 * 2 + off);
            }
#pragma unroll
            for (int p = 0; p < 4; p++) {
                uint32_t off = (uint32_t)((p * 16 + lr) * PAD) * 2 + koff;
                uint32_t r0, r1, r2, r3;
                ldm4(r0, r1, r2, r3, abase + 20480 * 2 + off);
                bb[2 * p][0] = r0; bb[2 * p][1] = r2;
                bb[2 * p + 1][0] = r1; bb[2 * p + 1][1] = r3;
            }
#pragma unroll
            for (int mi = 0; mi < 2; mi++)
#pragma unroll
                for (int ni = 0; ni < 8; ni++) mma_bf16(acc[mi][ni], ah[mi], bb[ni]);
#pragma unroll
            for (int mi = 0; mi < 2; mi++)
#pragma unroll
                for (int ni = 0; ni < 8; ni++) mma_bf16(acc[mi][ni], al[mi], bb[ni]);
#pragma unroll
            for (int p = 0; p < 4; p++) {
                uint32_t off = (uint32_t)((p * 16 + lr) * PAD) * 2 + koff;
                uint32_t r0, r1, r2, r3;
                ldm4(r0, r1, r2, r3, abase + 23040 * 2 + off);
                bb[2 * p][0] = r0; bb[2 * p][1] = r2;
                bb[2 * p + 1][0] = r1; bb[2 * p + 1][1] = r3;
            }
#pragma unroll
            for (int mi = 0; mi < 2; mi++)
#pragma unroll
                for (int ni = 0; ni < 8; ni++) mma_bf16(acc[mi][ni], ah[mi], bb[ni]);
        }
    };

    load_stage(0, 0);
    CP_COMMIT();
    for (int kc = 0; kc < 8; kc++) {
        if (kc + 1 < 8) {
            load_stage((kc + 1) & 1, (kc + 1) * 32);
            CP_COMMIT();
            CP_WAIT(1);
        } else {
            CP_WAIT(0);
        }
        __syncthreads();
        compute(kc & 1);
        __syncthreads();
    }

    // ---- epilogue: reorder (h, n2l) -> col n2l*4+h in smem, coalesced out ----
    float* stg = (float*)dsm;     // [64][260]
#pragma unroll
    for (int mi = 0; mi < 2; mi++)
#pragma unroll
        for (int ni = 0; ni < 8; ni++) {
            int r = mh * 32 + mi * 16 + (lane >> 2);
            int n2l = ni * 8 + (lane & 3) * 2;
            stg[r * 260 + n2l * 4 + wh]           = acc[mi][ni][0];
            stg[r * 260 + (n2l + 1) * 4 + wh]     = acc[mi][ni][1];
            stg[(r + 8) * 260 + n2l * 4 + wh]     = acc[mi][ni][2];
            stg[(r + 8) * 260 + (n2l + 1) * 4 + wh] = acc[mi][ni][3];
        }
    __syncthreads();

#pragma unroll
    for (int i = 0; i < 16; i++) {
        int g = i * 256 + t;                    // 4096 float4 groups
        int r = g >> 6, c4 = (g & 63) * 4;
        float4 v = *(const float4*)&stg[r * 260 + c4];
        float4 bz = *(const float4*)(bias + bn2 * 4 + c4);
        v.x += bz.x; v.y += bz.y; v.z += bz.z; v.w += bz.w;
        *(float4*)(Y + (size_t)(bm + r) * 4096 + bn2 * 4 + c4) = v;
    }
}

// ========================= launch ==========================================
extern "C" void kernel_launch(void* const* d_in, const int* in_sizes, int n_in,
                              void* d_out, int out_size) {
    const float* x     = (const float*)d_in[0];
    const float* core0 = (const float*)d_in[1];
    const float* core1 = (const float*)d_in[2];
    const float* core2 = (const float*)d_in[3];
    const float* core3 = (const float*)d_in[4];
    const float* bias  = (const float*)d_in[5];
    float* y = (float*)d_out;

    cudaFuncSetAttribute(gemm1_mma, cudaFuncAttributeMaxDynamicSharedMemorySize, G1_SMEM);
    cudaFuncSetAttribute(gemm2_mma, cudaFuncAttributeMaxDynamicSharedMemorySize, G2_SMEM);

    conv_x_kernel<<<(MTOT * 1024) / 256, 256>>>(x);
    build_pp_kernel<<<(1024 * 1024) / 256, 256>>>(core2, core3);
    build_q2_kernel<<<(1024 * 256) / 256, 256>>>(core0, core1);

    gemm1_mma<<<dim3(8, 64), 256, G1_SMEM>>>();
    gemm2_mma<<<dim3(16, 128), 256, G2_SMEM>>>(bias, y);
}

// round 4
// speedup vs baseline: 2.0551x; 1.4002x over previous
#include <cuda_runtime.h>
#include <cuda_bf16.h>
#include <cstdint>

// ---------------------------------------------------------------------------
// TR_Linear via two bf16-split GEMMs on the tensor pipe (portable PTX:
// mma.sync.m16n8k16.bf16 / ldmatrix / cp.async).
//   Pp^T[n][i'] (1024x1024), n=(r2*16+r4)*4+h ;  C1 = x @ Pp  (K=1024)
//   Q2^T[n2][k] (1024x256),  k=r2*16+r4, n2=i0*32+i1
//   y[b, n2*4+h] = sum_k C1[b,k*4+h]*Q2[k,n2] + bias
// Precision: v = hi + lo (bf16); D += Ahi*Bhi + Ahi*Blo + Alo*Bhi (fp32 acc)
// R4: hoisted fragment loads, 4-stage (g1)/3-stage (g2) cp.async rings,
// one __syncthreads per K-chunk, Q2 fully resident in smem for gemm2.
// ---------------------------------------------------------------------------

#define MTOT 8192
#define PAD 40   // bf16 elems per 32-elem k-row (80B stride -> conflict-free ldmatrix)

typedef __nv_bfloat16 bf16;

__device__ bf16 g_xh[MTOT * 1024];
__device__ bf16 g_xl[MTOT * 1024];
__device__ bf16 g_pph[1024 * 1024];
__device__ bf16 g_ppl[1024 * 1024];
__device__ bf16 g_q2h[1024 * 256];
__device__ bf16 g_q2l[1024 * 256];
__device__ bf16 g_c1h[4 * MTOT * 256];   // [h][b][k2]
__device__ bf16 g_c1l[4 * MTOT * 256];

// ========================= PTX helpers (portable) ==========================
__device__ __forceinline__ void cp16(uint32_t dst, const void* src) {
    asm volatile("cp.async.cg.shared.global [%0], [%1], 16;" :: "r"(dst), "l"(src));
}
#define CP_COMMIT() asm volatile("cp.async.commit_group;" ::: "memory")
#define CP_WAIT(N)  asm volatile("cp.async.wait_group %0;" :: "n"(N) : "memory")

__device__ __forceinline__ void ldm4(uint32_t& r0, uint32_t& r1, uint32_t& r2, uint32_t& r3,
                                     uint32_t addr) {
    asm volatile("ldmatrix.sync.aligned.m8n8.x4.shared.b16 {%0,%1,%2,%3}, [%4];"
                 : "=r"(r0), "=r"(r1), "=r"(r2), "=r"(r3) : "r"(addr));
}
__device__ __forceinline__ void mma_bf16(float* d, const uint32_t* a, const uint32_t* b) {
    asm volatile("mma.sync.aligned.m16n8k16.row.col.f32.bf16.bf16.f32 "
                 "{%0,%1,%2,%3}, {%4,%5,%6,%7}, {%8,%9}, {%0,%1,%2,%3};"
                 : "+f"(d[0]), "+f"(d[1]), "+f"(d[2]), "+f"(d[3])
                 : "r"(a[0]), "r"(a[1]), "r"(a[2]), "r"(a[3]), "r"(b[0]), "r"(b[1]));
}
__device__ __forceinline__ uint32_t cvta_s(const void* p) {
    return (uint32_t)__cvta_generic_to_shared(p);
}
__device__ __forceinline__ void split2(float v, bf16& h, bf16& l) {
    h = __float2bfloat16_rn(v);
    l = __float2bfloat16_rn(v - __bfloat162float(h));
}

// ========================= prepass kernels =================================
__global__ void conv_x_kernel(const float* __restrict__ x) {
    int i = blockIdx.x * blockDim.x + threadIdx.x;
    bf16 h, l;
    split2(x[i], h, l);
    g_xh[i] = h;
    g_xl[i] = l;
}

__global__ void build_pp_kernel(const float* __restrict__ c2, const float* __restrict__ c3) {
    int idx = blockIdx.x * blockDim.x + threadIdx.x;   // n*1024 + i'
    int n = idx >> 10, ip = idx & 1023;
    int r2 = n >> 6, r4 = (n >> 2) & 15, h = n & 3;
    int o0 = h * 16 + (ip >> 6), o1 = ip & 63;
    const float* a = c2 + (r2 * 64 + o0) * 16;
    float s = 0.f;
#pragma unroll
    for (int r3 = 0; r3 < 16; r3++) s += a[r3] * c3[(r3 * 64 + o1) * 16 + r4];
    bf16 hh, ll;
    split2(s, hh, ll);
    g_pph[idx] = hh;
    g_ppl[idx] = ll;
}

__global__ void build_q2_kernel(const float* __restrict__ c0, const float* __restrict__ c1) {
    int idx = blockIdx.x * blockDim.x + threadIdx.x;   // n2*256 + k
    int n2 = idx >> 8, k = idx & 255;
    int r2 = k >> 4, r4 = k & 15;
    int i0 = n2 >> 5, i1 = n2 & 31;
    const float* a = c0 + (r4 * 32 + i0) * 16;
    float s = 0.f;
#pragma unroll
    for (int r1 = 0; r1 < 16; r1++) s += a[r1] * c1[(r1 * 32 + i1) * 16 + r2];
    bf16 hh, ll;
    split2(s, hh, ll);
    g_q2h[idx] = hh;
    g_q2l[idx] = ll;
}

// ========================= GEMM1: C1 = x @ Pp ==============================
// 128x128 block, K=1024 in 32 chunks of 32. Per stage (bf16 units):
// Ah @0, Al @128*PAD, Bh @2*128*PAD, Bl @3*128*PAD. 4-stage ring.
#define G1_SLOT (4 * 128 * PAD)            // 20480 bf16 = 40960 B
#define G1_STAGES 4
#define G1_SMEM (G1_STAGES * G1_SLOT * 2)  // 163840 B

__global__ __launch_bounds__(256, 1) void gemm1_mma() {
    extern __shared__ char dsm[];
    bf16* sm = (bf16*)dsm;
    const int t = threadIdx.x, wid = t >> 5, lane = t & 31;
    const int bm = blockIdx.y * 128, bn = blockIdx.x * 128;
    const int wm = wid & 1, wn = wid >> 1;     // warp tile 64m x 32n

    float acc[4][4][4];
#pragma unroll
    for (int a = 0; a < 4; a++)
#pragma unroll
        for (int b = 0; b < 4; b++)
#pragma unroll
            for (int c = 0; c < 4; c++) acc[a][b][c] = 0.f;

    auto load_stage = [&](int s, int k0) {
#pragma unroll
        for (int i = 0; i < 8; i++) {
            int gi = i * 256 + t;
            int arr = gi >> 9, rem = gi & 511, row = rem >> 2, c = rem & 3;
            const bf16* src;
            if (arr == 0)      src = g_xh  + (size_t)(bm + row) * 1024 + k0 + c * 8;
            else if (arr == 1) src = g_xl  + (size_t)(bm + row) * 1024 + k0 + c * 8;
            else if (arr == 2) src = g_pph + (size_t)(bn + row) * 1024 + k0 + c * 8;
            else               src = g_ppl + (size_t)(bn + row) * 1024 + k0 + c * 8;
            cp16(cvta_s(sm + s * G1_SLOT + arr * 128 * PAD + row * PAD + c * 8), src);
        }
    };

    const int lr = lane & 15, lc = lane >> 4;

    auto compute = [&](int s) {
        uint32_t abase = cvta_s(sm) + (uint32_t)(s * G1_SLOT) * 2;
        uint32_t ah[2][4][4], al[2][4][4], bh[2][4][2], bl[2][4][2];
        // ---- hoisted fragment loads (deep LDSM batch) ----
#pragma unroll
        for (int kk = 0; kk < 2; kk++) {
            uint32_t koff = (uint32_t)((kk * 2 + lc) * 8) * 2;
#pragma unroll
            for (int mi = 0; mi < 4; mi++) {
                uint32_t off = (uint32_t)((wm * 64 + mi * 16 + lr) * PAD) * 2 + koff;
                ldm4(ah[kk][mi][0], ah[kk][mi][1], ah[kk][mi][2], ah[kk][mi][3], abase + off);
                ldm4(al[kk][mi][0], al[kk][mi][1], al[kk][mi][2], al[kk][mi][3],
                     abase + 128 * PAD * 2 + off);
            }
#pragma unroll
            for (int p = 0; p < 2; p++) {
                uint32_t off = (uint32_t)((wn * 32 + p * 16 + lr) * PAD) * 2 + koff;
                uint32_t r0, r1, r2, r3;
                ldm4(r0, r1, r2, r3, abase + 2 * 128 * PAD * 2 + off);
                bh[kk][2 * p][0] = r0; bh[kk][2 * p][1] = r2;
                bh[kk][2 * p + 1][0] = r1; bh[kk][2 * p + 1][1] = r3;
                ldm4(r0, r1, r2, r3, abase + 3 * 128 * PAD * 2 + off);
                bl[kk][2 * p][0] = r0; bl[kk][2 * p][1] = r2;
                bl[kk][2 * p + 1][0] = r1; bl[kk][2 * p + 1][1] = r3;
            }
        }
        // ---- uninterrupted MMA stream: 96 HMMA ----
#pragma unroll
        for (int kk = 0; kk < 2; kk++)
#pragma unroll
            for (int mi = 0; mi < 4; mi++)
#pragma unroll
                for (int ni = 0; ni < 4; ni++) {
                    mma_bf16(acc[mi][ni], ah[kk][mi], bh[kk][ni]);
                    mma_bf16(acc[mi][ni], al[kk][mi], bh[kk][ni]);
                    mma_bf16(acc[mi][ni], ah[kk][mi], bl[kk][ni]);
                }
    };

#pragma unroll
    for (int s = 0; s < G1_STAGES - 1; s++) {
        load_stage(s, s * 32);
        CP_COMMIT();
    }
    for (int kc = 0; kc < 32; kc++) {
        CP_WAIT(2);
        __syncthreads();
        compute(kc & 3);
        if (kc + G1_STAGES - 1 < 32) load_stage((kc + G1_STAGES - 1) & 3, (kc + 3) * 32);
        CP_COMMIT();
    }

    // ---- epilogue: stage fp32 tile, then bf16-split into C1[h][b][k2] ----
    __syncthreads();
    float* stg = (float*)dsm;     // [128][132]
#pragma unroll
    for (int mi = 0; mi < 4; mi++)
#pragma unroll
        for (int ni = 0; ni < 4; ni++) {
            int r = wm * 64 + mi * 16 + (lane >> 2);
            int c = wn * 32 + ni * 8 + (lane & 3) * 2;
            stg[r * 132 + c]           = acc[mi][ni][0];
            stg[r * 132 + c + 1]       = acc[mi][ni][1];
            stg[(r + 8) * 132 + c]     = acc[mi][ni][2];
            stg[(r + 8) * 132 + c + 1] = acc[mi][ni][3];
        }
    __syncthreads();

    const int kb = bn >> 2;
#pragma unroll
    for (int i = 0; i < 16; i++) {
        int g = i * 256 + t;                   // 4096 groups of 4 k2
        int row = g >> 5, rem = g & 31, h = rem >> 3, kg = rem & 7;
        ushort4 vh, vl;
        bf16 hh, ll;
        split2(stg[row * 132 + (kg * 4 + 0) * 4 + h], hh, ll);
        vh.x = __bfloat16_as_ushort(hh); vl.x = __bfloat16_as_ushort(ll);
        split2(stg[row * 132 + (kg * 4 + 1) * 4 + h], hh, ll);
        vh.y = __bfloat16_as_ushort(hh); vl.y = __bfloat16_as_ushort(ll);
        split2(stg[row * 132 + (kg * 4 + 2) * 4 + h], hh, ll);
        vh.z = __bfloat16_as_ushort(hh); vl.z = __bfloat16_as_ushort(ll);
        split2(stg[row * 132 + (kg * 4 + 3) * 4 + h], hh, ll);
        vh.w = __bfloat16_as_ushort(hh); vl.w = __bfloat16_as_ushort(ll);
        size_t o = ((size_t)h * MTOT + bm + row) * 256 + kb + kg * 4;
        *(ushort4*)(g_c1h + o) = vh;
        *(ushort4*)(g_c1l + o) = vl;
    }
}

// ========================= GEMM2: y = C1_h @ Q2^T + bias ===================
// Block: 64b x 64n2 x 4h. K=256 in 8 chunks of 32.
// Q2 (B) resident for full K: rows 64, BPAD=264 elems (528B stride, odd*16B).
// A ring: 3 stages, per stage 2 planes x (4h*64 rows) x PAD.
#define G2_SLOT (2 * 4 * 64 * PAD)          // 20480 bf16 = 40960 B
#define G2_STAGES 3
#define BPAD 264
#define BOFF (G2_STAGES * G2_SLOT)          // 61440 bf16
#define BPLANE (64 * BPAD)                  // 16896 bf16
#define G2_SMEM ((BOFF + 2 * BPLANE) * 2)   // 190464 B

__global__ __launch_bounds__(256, 1) void gemm2_mma(const float* __restrict__ bias,
                                                    float* __restrict__ Y) {
    extern __shared__ char dsm[];
    bf16* sm = (bf16*)dsm;
    const int t = threadIdx.x, wid = t >> 5, lane = t & 31;
    const int bm = blockIdx.y * 64, bn2 = blockIdx.x * 64;
    const int wh = wid >> 1, mh = wid & 1;     // warp: h = wh, rows mh*32..+31

    float acc[2][8][4];
#pragma unroll
    for (int a = 0; a < 2; a++)
#pragma unroll
        for (int b = 0; b < 8; b++)
#pragma unroll
            for (int c = 0; c < 4; c++) acc[a][b][c] = 0.f;

    auto load_B = [&]() {       // full-K Q2, both planes, once
#pragma unroll
        for (int i = 0; i < 16; i++) {
            int gi = i * 256 + t;                    // 4096 x 16B
            int plane = gi >> 11, rem = gi & 2047, row = rem >> 5, c = rem & 31;
            const bf16* src = (plane ? g_q2l : g_q2h) + (size_t)(bn2 + row) * 256 + c * 8;
            cp16(cvta_s(sm + BOFF + plane * BPLANE + row * BPAD + c * 8), src);
        }
    };
    auto load_A = [&](int s, int k0) {
#pragma unroll
        for (int i = 0; i < 8; i++) {
            int gi = i * 256 + t;                    // 2048 x 16B
            int plane = gi >> 10, rem = gi & 1023;
            int h = rem >> 8, rem2 = rem & 255, row = rem2 >> 2, c = rem2 & 3;
            const bf16* src = (plane ? g_c1l : g_c1h) +
                ((size_t)h * MTOT + bm + row) * 256 + k0 + c * 8;
            cp16(cvta_s(sm + s * G2_SLOT + plane * (4 * 64 * PAD) + (h * 64 + row) * PAD + c * 8), src);
        }
    };

    const int lr = lane & 15, lc = lane >> 4;

    auto compute = [&](int s, int kc) {
        uint32_t abase = cvta_s(sm) + (uint32_t)(s * G2_SLOT) * 2;
        uint32_t bbase = cvta_s(sm) + (uint32_t)BOFF * 2;
        uint32_t ah[2][2][4], al[2][2][4], bh[2][8][2], bl[2][8][2];
#pragma unroll
        for (int kk = 0; kk < 2; kk++) {
            uint32_t koff = (uint32_t)((kk * 2 + lc) * 8) * 2;
#pragma unroll
            for (int mi = 0; mi < 2; mi++) {
                uint32_t off = (uint32_t)((wh * 64 + mh * 32 + mi * 16 + lr) * PAD) * 2 + koff;
                ldm4(ah[kk][mi][0], ah[kk][mi][1], ah[kk][mi][2], ah[kk][mi][3], abase + off);
                ldm4(al[kk][mi][0], al[kk][mi][1], al[kk][mi][2], al[kk][mi][3],
                     abase + (4 * 64 * PAD) * 2 + off);
            }
            uint32_t kb = (uint32_t)(kc * 32 + (kk * 2 + lc) * 8) * 2;
#pragma unroll
            for (int p = 0; p < 4; p++) {
                uint32_t off = (uint32_t)((p * 16 + lr) * BPAD) * 2 + kb;
                uint32_t r0, r1, r2, r3;
                ldm4(r0, r1, r2, r3, bbase + off);
                bh[kk][2 * p][0] = r0; bh[kk][2 * p][1] = r2;
                bh[kk][2 * p + 1][0] = r1; bh[kk][2 * p + 1][1] = r3;
                ldm4(r0, r1, r2, r3, bbase + BPLANE * 2 + off);
                bl[kk][2 * p][0] = r0; bl[kk][2 * p][1] = r2;
                bl[kk][2 * p + 1][0] = r1; bl[kk][2 * p + 1][1] = r3;
            }
        }
#pragma unroll
        for (int kk = 0; kk < 2; kk++)
#pragma unroll
            for (int mi = 0; mi < 2; mi++)
#pragma unroll
                for (int ni = 0; ni < 8; ni++) {
                    mma_bf16(acc[mi][ni], ah[kk][mi], bh[kk][ni]);
                    mma_bf16(acc[mi][ni], al[kk][mi], bh[kk][ni]);
                    mma_bf16(acc[mi][ni], ah[kk][mi], bl[kk][ni]);
                }
    };

    load_B();
    load_A(0, 0);
    CP_COMMIT();                 // group 0: B + A0
    load_A(1, 32);
    CP_COMMIT();                 // group 1: A1
    for (int kc = 0; kc < 8; kc++) {
        CP_WAIT(1);
        __syncthreads();
        compute(kc % 3, kc);
        if (kc + 2 < 8) load_A((kc + 2) % 3, (kc + 2) * 32);
        CP_COMMIT();
    }

    // ---- epilogue: reorder (h, n2l) -> col n2l*4+h in smem, coalesced out ----
    __syncthreads();
    float* stg = (float*)dsm;     // [64][260]
#pragma unroll
    for (int mi = 0; mi < 2; mi++)
#pragma unroll
        for (int ni = 0; ni < 8; ni++) {
            int r = mh * 32 + mi * 16 + (lane >> 2);
            int n2l = ni * 8 + (lane & 3) * 2;
            stg[r * 260 + n2l * 4 + wh]             = acc[mi][ni][0];
            stg[r * 260 + (n2l + 1) * 4 + wh]       = acc[mi][ni][1];
            stg[(r + 8) * 260 + n2l * 4 + wh]       = acc[mi][ni][2];
            stg[(r + 8) * 260 + (n2l + 1) * 4 + wh] = acc[mi][ni][3];
        }
    __syncthreads();

#pragma unroll
    for (int i = 0; i < 16; i++) {
        int g = i * 256 + t;                    // 4096 float4 groups
        int r = g >> 6, c4 = (g & 63) * 4;
        float4 v = *(const float4*)&stg[r * 260 + c4];
        float4 bz = *(const float4*)(bias + bn2 * 4 + c4);
        v.x += bz.x; v.y += bz.y; v.z += bz.z; v.w += bz.w;
        *(float4*)(Y + (size_t)(bm + r) * 4096 + bn2 * 4 + c4) = v;
    }
}

// ========================= launch ==========================================
extern "C" void kernel_launch(void* const* d_in, const int* in_sizes, int n_in,
                              void* d_out, int out_size) {
    const float* x     = (const float*)d_in[0];
    const float* core0 = (const float*)d_in[1];
    const float* core1 = (const float*)d_in[2];
    const float* core2 = (const float*)d_in[3];
    const float* core3 = (const float*)d_in[4];
    const float* bias  = (const float*)d_in[5];
    float* y = (float*)d_out;

    cudaFuncSetAttribute(gemm1_mma, cudaFuncAttributeMaxDynamicSharedMemorySize, G1_SMEM);
    cudaFuncSetAttribute(gemm2_mma, cudaFuncAttributeMaxDynamicSharedMemorySize, G2_SMEM);

    conv_x_kernel<<<(MTOT * 1024) / 256, 256>>>(x);
    build_pp_kernel<<<(1024 * 1024) / 256, 256>>>(core2, core3);
    build_q2_kernel<<<(1024 * 256) / 256, 256>>>(core0, core1);

    gemm1_mma<<<dim3(8, 64), 256, G1_SMEM>>>();
    gemm2_mma<<<dim3(16, 128), 256, G2_SMEM>>>(bias, y);
}